// round 11
// baseline (speedup 1.0000x reference)
#include <cuda_runtime.h>
#include <cuda_bf16.h>
#include <cuda_fp16.h>
#include <cstdint>

#define NB 4
#define NN 10000
#define NE 170000
#define FIN 256
#define FOUT 128
#define NH 4
#define MTOT (NB*NN)          /* 40000 */
#define LEAKY 0.2f

// ---------------- scratch (static device memory; no allocs allowed) --------
__device__ __half  d_x16[(size_t)MTOT * FIN];  // x fp16, rows = b*NN+n (20.5 MB)
__device__ __half  d_g[(size_t)NH * MTOT * FIN]; // aggregated x, [h][n*4+b][k] (82 MB)
__device__ float   d_bsc[NN];                  // 1 if node has edges else 0
__device__ float4  d_ev[NE];                   // exp(att) per edge, 4 heads packed
__device__ float4  d_ps[NN];
__device__ float4  d_pd[NN];
__device__ int     d_rowptr[NN + 1];
__device__ float   d_vsrc[NH * FIN];
__device__ float   d_vdst[NH * FIN];
__device__ float   d_csrc[NH];
__device__ float   d_cdst[NH];
// fp16 W transposed to [h][n][k] for the tensor-core GEMM
__device__ __half  d_Bf[NH * FOUT * FIN];

__device__ __forceinline__ uint32_t smem_u32(const void* p) {
    uint32_t a;
    asm("{ .reg .u64 t; cvta.to.shared.u64 t, %1; cvt.u32.u64 %0, t; }" : "=r"(a) : "l"(p));
    return a;
}

// ---------------- K-1: x -> fp16 -------------------------------------------
__global__ void conv_x16(const float* __restrict__ x) {
    int i = blockIdx.x * blockDim.x + threadIdx.x;   // 8 elems per thread
    if (i >= MTOT * FIN / 8) return;
    float4 v0 = ((const float4*)x)[2 * i];
    float4 v1 = ((const float4*)x)[2 * i + 1];
    uint4 o;
    __half2 p;
    p = __floats2half2_rn(v0.x, v0.y); o.x = *(uint32_t*)&p;
    p = __floats2half2_rn(v0.z, v0.w); o.y = *(uint32_t*)&p;
    p = __floats2half2_rn(v1.x, v1.y); o.z = *(uint32_t*)&p;
    p = __floats2half2_rn(v1.z, v1.w); o.w = *(uint32_t*)&p;
    ((uint4*)d_x16)[i] = o;
}

// ---------------- K0: W fp16 transpose + attention-vector fold (fused) -----
__global__ void prep_all(const float* __restrict__ Wm, const float* __restrict__ bm,
                         const float* __restrict__ Wa) {
    if (blockIdx.x < 512) {
        int i = blockIdx.x * 256 + threadIdx.x;      // [h][k][f]
        int h = i >> 15;
        int rem = i & 32767;
        int k = rem >> 7;
        int f = rem & 127;
        size_t o = ((size_t)h * FOUT + f) * FIN + k; // [h][n][k]
        d_Bf[o] = __float2half_rn(Wm[i]);
        return;
    }
    int h = blockIdx.x - 512;
    int t = threadIdx.x;
    __shared__ float asrc[FOUT], adst[FOUT];
    if (t < FOUT) {
        asrc[t] = Wa[h * 2 * FOUT + t];
        adst[t] = Wa[h * 2 * FOUT + FOUT + t];
    }
    __syncthreads();
    const float* w = Wm + (size_t)h * FIN * FOUT + (size_t)t * FOUT;
    float s1 = 0.f, s2 = 0.f;
#pragma unroll 8
    for (int f = 0; f < FOUT; f++) {
        float wv = w[f];
        s1 += wv * asrc[f];
        s2 += wv * adst[f];
    }
    d_vsrc[h * FIN + t] = s1;
    d_vdst[h * FIN + t] = s2;
    if (t == 0) {
        float c1 = 0.f, c2 = 0.f;
        for (int f = 0; f < FOUT; f++) {
            float bv = bm[h * FOUT + f];
            c1 += bv * asrc[f];
            c2 += bv * adst[f];
        }
        d_csrc[h] = c1;
        d_cdst[h] = c2;
    }
}

// ---------------- K1: per-node scores, warp per node -----------------------
__global__ void node_scores(const float* __restrict__ Xl) {
    int gw = (blockIdx.x * blockDim.x + threadIdx.x) >> 5;
    int lane = threadIdx.x & 31;
    if (gw >= NN) return;
    const float* xr = Xl + (size_t)gw * FIN;
    float xv[8];
#pragma unroll
    for (int i = 0; i < 8; i++) xv[i] = xr[lane + 32 * i];
    float ps[NH], pd[NH];
#pragma unroll
    for (int h = 0; h < NH; h++) {
        float s1 = 0.f, s2 = 0.f;
#pragma unroll
        for (int i = 0; i < 8; i++) {
            int k = lane + 32 * i;
            s1 += xv[i] * d_vsrc[h * FIN + k];
            s2 += xv[i] * d_vdst[h * FIN + k];
        }
#pragma unroll
        for (int o = 16; o > 0; o >>= 1) {
            s1 += __shfl_down_sync(0xffffffffu, s1, o);
            s2 += __shfl_down_sync(0xffffffffu, s2, o);
        }
        ps[h] = s1;
        pd[h] = s2;
    }
    if (lane == 0) {
        d_ps[gw] = make_float4(ps[0] + d_csrc[0], ps[1] + d_csrc[1],
                               ps[2] + d_csrc[2], ps[3] + d_csrc[3]);
        d_pd[gw] = make_float4(pd[0] + d_cdst[0], pd[1] + d_cdst[1],
                               pd[2] + d_cdst[2], pd[3] + d_cdst[3]);
    }
}

// ---------------- K2: per-edge exp + CSR row_ptr (fused) -------------------
__device__ __forceinline__ float att_act(float s) {
    float lr = s > 0.f ? s : LEAKY * s;
    lr = fminf(fmaxf(lr, -2.f), 2.f);
    return expf(lr);
}

__global__ void edge_prep(const int* __restrict__ src, const int* __restrict__ dst) {
    int e = blockIdx.x * blockDim.x + threadIdx.x;
    if (e >= NE) return;
    int cur = src[e];
    float4 a = d_ps[cur];
    float4 b = d_pd[dst[e]];
    d_ev[e] = make_float4(att_act(a.x + b.x), att_act(a.y + b.y),
                          att_act(a.z + b.z), att_act(a.w + b.w));
    int prev = (e == 0) ? -1 : src[e - 1];
    for (int n = prev + 1; n <= cur; n++) d_rowptr[n] = e;
    if (e == NE - 1)
        for (int n = cur + 1; n <= NN; n++) d_rowptr[n] = NE;
}

// ---------------- K3: x-space aggregation, block per node ------------------
// g[n][h][b][k] = sum_e w^h_e x16[dst_e][b][k], normalized by sum_e w^h_e,
// stored fp16 to d_g[h][n*4+b][k].
#define CHK 128
__global__ __launch_bounds__(256) void aggx(const int* __restrict__ dst) {
    const int n = blockIdx.x;
    const int r0 = d_rowptr[n];
    const int r1 = d_rowptr[n + 1];
    const int t = threadIdx.x;
    __shared__ int sdst[CHK];
    __shared__ float4 sev[CHK];
    __shared__ float4 sred[128];

    // ---- phase 0: denominators (segment sum of ev over this node's edges)
    float4 p = make_float4(0.f, 0.f, 0.f, 0.f);
    if (t < 128)
        for (int e = r0 + t; e < r1; e += 128) {
            float4 v = d_ev[e];
            p.x += v.x; p.y += v.y; p.z += v.z; p.w += v.w;
        }
    if (t < 128) sred[t] = p;
    __syncthreads();
    if (t < 32) {
        float4 a = sred[t], b = sred[t + 32], c = sred[t + 64], d = sred[t + 96];
        float4 s = make_float4(a.x + b.x + c.x + d.x, a.y + b.y + c.y + d.y,
                               a.z + b.z + c.z + d.z, a.w + b.w + c.w + d.w);
#pragma unroll
        for (int o = 16; o > 0; o >>= 1) {
            s.x += __shfl_down_sync(0xffffffffu, s.x, o);
            s.y += __shfl_down_sync(0xffffffffu, s.y, o);
            s.z += __shfl_down_sync(0xffffffffu, s.z, o);
            s.w += __shfl_down_sync(0xffffffffu, s.w, o);
        }
        if (t == 0) {
            float4 inv;
            if (r1 > r0) {
                inv = make_float4(1.0f / s.x, 1.0f / s.y, 1.0f / s.z, 1.0f / s.w);
            } else {
                inv = make_float4(0.f, 0.f, 0.f, 0.f);
            }
            sred[0] = inv;
            d_bsc[n] = (r1 > r0) ? 1.f : 0.f;
        }
    }
    __syncthreads();
    const float4 inv4 = sred[0];

    // ---- phase 1: weighted accumulate of x[dst] ----
    const int bb = t >> 6;               // batch
    const int kq = (t & 63) * 4;         // 4 halves of this thread
    const __half* xb = d_x16 + (size_t)bb * NN * FIN + kq;
    float acc[4][4];
#pragma unroll
    for (int h = 0; h < 4; h++)
#pragma unroll
        for (int j = 0; j < 4; j++) acc[h][j] = 0.f;

    for (int base = r0; base < r1; base += CHK) {
        int cnt = min(CHK, r1 - base);
        __syncthreads();
        if (t < cnt) {
            sdst[t] = dst[base + t];
            sev[t] = d_ev[base + t];
        }
        __syncthreads();
        int i = 0;
        for (; i + 1 < cnt; i += 2) {
            uint2 u0 = *(const uint2*)(xb + (size_t)sdst[i] * FIN);
            uint2 u1 = *(const uint2*)(xb + (size_t)sdst[i + 1] * FIN);
            float4 w0 = sev[i], w1 = sev[i + 1];
            float2 a0 = __half22float2(*(__half2*)&u0.x);
            float2 a1 = __half22float2(*(__half2*)&u0.y);
            float2 b0 = __half22float2(*(__half2*)&u1.x);
            float2 b1 = __half22float2(*(__half2*)&u1.y);
            const float* w0p = (const float*)&w0;
            const float* w1p = (const float*)&w1;
#pragma unroll
            for (int h = 0; h < 4; h++) {
                float wa = w0p[h], wb = w1p[h];
                acc[h][0] = fmaf(wa, a0.x, acc[h][0]);
                acc[h][1] = fmaf(wa, a0.y, acc[h][1]);
                acc[h][2] = fmaf(wa, a1.x, acc[h][2]);
                acc[h][3] = fmaf(wa, a1.y, acc[h][3]);
                acc[h][0] = fmaf(wb, b0.x, acc[h][0]);
                acc[h][1] = fmaf(wb, b0.y, acc[h][1]);
                acc[h][2] = fmaf(wb, b1.x, acc[h][2]);
                acc[h][3] = fmaf(wb, b1.y, acc[h][3]);
            }
        }
        if (i < cnt) {
            uint2 u0 = *(const uint2*)(xb + (size_t)sdst[i] * FIN);
            float4 w0 = sev[i];
            float2 a0 = __half22float2(*(__half2*)&u0.x);
            float2 a1 = __half22float2(*(__half2*)&u0.y);
            const float* w0p = (const float*)&w0;
#pragma unroll
            for (int h = 0; h < 4; h++) {
                float wa = w0p[h];
                acc[h][0] = fmaf(wa, a0.x, acc[h][0]);
                acc[h][1] = fmaf(wa, a0.y, acc[h][1]);
                acc[h][2] = fmaf(wa, a1.x, acc[h][2]);
                acc[h][3] = fmaf(wa, a1.y, acc[h][3]);
            }
        }
    }

    // ---- store normalized fp16 ----
    const float iv[4] = {inv4.x, inv4.y, inv4.z, inv4.w};
    const size_t rowbase = (size_t)(n * 4 + bb) * FIN + kq;
#pragma unroll
    for (int h = 0; h < 4; h++) {
        __half2 lo = __floats2half2_rn(acc[h][0] * iv[h], acc[h][1] * iv[h]);
        __half2 hi = __floats2half2_rn(acc[h][2] * iv[h], acc[h][3] * iv[h]);
        uint2 st;
        st.x = *(uint32_t*)&lo;
        st.y = *(uint32_t*)&hi;
        *(uint2*)(d_g + (size_t)h * MTOT * FIN + rowbase) = st;
    }
}

// ---------------- K4: barrier-free fp16 GEMM: out = g @ W + b --------------
// CTA: 256 thr / 8 warps; tile M=128 x N=128 (one head), full K=256 resident.
// B (=W) in smem once; A fragments via direct LDG.32 from d_g (fp16).
#define ROWB 528                      /* 256 fp16 = 512 B + 16 pad */
#define SM_TOTAL (128 * ROWB)         /* 67584 bytes */

#define MMA_F16(d, a, b)                                                       \
    asm volatile("mma.sync.aligned.m16n8k16.row.col.f32.f16.f16.f32 "          \
                 "{%0,%1,%2,%3},{%4,%5,%6,%7},{%8,%9},{%0,%1,%2,%3};"          \
                 : "+f"((d)[0]), "+f"((d)[1]), "+f"((d)[2]), "+f"((d)[3])      \
                 : "r"((a)[0]), "r"((a)[1]), "r"((a)[2]), "r"((a)[3]),         \
                   "r"((b)[0]), "r"((b)[1]))

#define LDSM4(r0, r1, r2, r3, addr)                                            \
    asm volatile("ldmatrix.sync.aligned.m8n8.x4.shared.b16 {%0,%1,%2,%3},[%4];"\
                 : "=r"(r0), "=r"(r1), "=r"(r2), "=r"(r3) : "r"(addr))

__global__ __launch_bounds__(256, 2) void gemm_out(float* __restrict__ out,
                                                   const float* __restrict__ bm) {
    extern __shared__ char smem[];
    const uint32_t sb32 = smem_u32(smem);
    const int tid = threadIdx.x;
    const int hx = blockIdx.x;
    const int row0 = blockIdx.y * 128;
    const int wid = tid >> 5;
    const int lane = tid & 31;
    const int gid = lane >> 2;
    const int tig = lane & 3;
    const int warpM = wid & 3;
    const int warpN = wid >> 2;

    // ---- load the full B tile (128 x 256 fp16 = 512 B/row) once ----
    {
        const int r = tid >> 1;
        const int half = tid & 1;
        const __half* bsrc = d_Bf + ((size_t)hx * FOUT + r) * FIN + half * 128;
        char* brow = smem + r * ROWB + half * 256;
#pragma unroll
        for (int j = 0; j < 16; j++)
            *(uint4*)(brow + j * 16) = *(const uint4*)(bsrc + j * 8);
    }
    __syncthreads();

    // B ldmatrix lane addressing
    const uint32_t bN = (uint32_t)(warpN * 64 + (lane & 7) + ((lane & 16) ? 8 : 0));
    const uint32_t bKof = (uint32_t)((lane & 8) ? 8 : 0);
    const uint32_t bBase = sb32 + bN * ROWB + bKof * 2;

    // A row pointers into d_g[hx] (clamped; OOB rows masked at epilogue)
    const __half* gbase = d_g + (size_t)hx * MTOT * FIN;
    const __half* rp[2][2];
#pragma unroll
    for (int mt = 0; mt < 2; mt++)
#pragma unroll
        for (int rh = 0; rh < 2; rh++) {
            int gr = row0 + warpM * 32 + mt * 16 + rh * 8 + gid;
            gr = gr < MTOT ? gr : MTOT - 1;
            rp[mt][rh] = gbase + (size_t)gr * FIN + tig * 2;
        }

    float acc[2][8][4];
#pragma unroll
    for (int mt = 0; mt < 2; mt++)
#pragma unroll
        for (int nt = 0; nt < 8; nt++)
#pragma unroll
            for (int j = 0; j < 4; j++) acc[mt][nt][j] = 0.f;

#pragma unroll
    for (int ks = 0; ks < 16; ks++) {
        const int k0 = ks * 16;
        uint32_t af[2][4], bf[8][2];
#pragma unroll
        for (int mt = 0; mt < 2; mt++) {
            af[mt][0] = *(const uint32_t*)(rp[mt][0] + k0);
            af[mt][1] = *(const uint32_t*)(rp[mt][1] + k0);
            af[mt][2] = *(const uint32_t*)(rp[mt][0] + k0 + 8);
            af[mt][3] = *(const uint32_t*)(rp[mt][1] + k0 + 8);
        }
#pragma unroll
        for (int p4 = 0; p4 < 4; p4++)
            LDSM4(bf[2 * p4][0], bf[2 * p4][1], bf[2 * p4 + 1][0], bf[2 * p4 + 1][1],
                  bBase + (uint32_t)(p4 * 16 * ROWB + k0 * 2));
#pragma unroll
        for (int mt = 0; mt < 2; mt++)
#pragma unroll
            for (int nt = 0; nt < 8; nt++) MMA_F16(acc[mt][nt], af[mt], bf[nt]);
    }

    // ---- epilogue: +bias (masked for zero-edge nodes), write out fp32 ----
    float2 bias[8];
#pragma unroll
    for (int nt = 0; nt < 8; nt++)
        bias[nt] = *(const float2*)(bm + hx * FOUT + warpN * 64 + nt * 8 + tig * 2);

#pragma unroll
    for (int mt = 0; mt < 2; mt++) {
#pragma unroll
        for (int rh = 0; rh < 2; rh++) {
            int gr = row0 + warpM * 32 + mt * 16 + rh * 8 + gid;
            if (gr >= MTOT) continue;
            int n = gr >> 2;
            int bb = gr & 3;
            float bs = d_bsc[n];
            float* dp = out + (size_t)bb * NN * (NH * FOUT) + (size_t)n * (NH * FOUT)
                        + hx * FOUT + warpN * 64 + tig * 2;
#pragma unroll
            for (int nt = 0; nt < 8; nt++) {
                float2 v;
                v.x = acc[mt][nt][rh * 2 + 0] + bias[nt].x * bs;
                v.y = acc[mt][nt][rh * 2 + 1] + bias[nt].y * bs;
                *(float2*)(dp + nt * 8) = v;
            }
        }
    }
}

// ---------------------------------------------------------------------------
extern "C" void kernel_launch(void* const* d_in, const int* in_sizes, int n_in,
                              void* d_out, int out_size) {
    const float* x   = (const float*)d_in[0];   // (B, N, 256)
    const float* Wm  = (const float*)d_in[1];   // (H, 256, 128)
    const float* bm  = (const float*)d_in[2];   // (H, 128)
    const float* Wa  = (const float*)d_in[3];   // (H, 256, 1)
    const int*   src = (const int*)d_in[4];     // (E,) sorted
    const int*   dst = (const int*)d_in[5];     // (E,)
    float* out = (float*)d_out;                 // (B, N, 512)

    cudaFuncSetAttribute(gemm_out, cudaFuncAttributeMaxDynamicSharedMemorySize, SM_TOTAL);

    prep_all<<<516, 256>>>(Wm, bm, Wa);
    conv_x16<<<(MTOT * FIN / 8 + 255) / 256, 256>>>(x);
    node_scores<<<(NN * 32 + 255) / 256, 256>>>(x + (size_t)(NB - 1) * NN * FIN);
    edge_prep<<<(NE + 255) / 256, 256>>>(src, dst);
    aggx<<<NN, 256>>>(dst);
    dim3 gg(NH, (MTOT + 127) / 128);
    gemm_out<<<gg, 256, SM_TOTAL>>>(out, bm);
}